// round 17
// baseline (speedup 1.0000x reference)
#include <cuda_runtime.h>
#include <cuda_bf16.h>
#include <stdint.h>
#include <math.h>

#define NEG_INF (-1e9f)

#define Bsz 32
#define LQ  1024
#define LK  1024
#define DIM 1024
#define HB  (Bsz / 2)   // batches per pipeline half

typedef __nv_bfloat16  bf16;
typedef __nv_bfloat162 bf162;

// ---------------------------------------------------------------------------
// Scratch (__device__ globals; allocation-free rule).
// ---------------------------------------------------------------------------
__device__ bf16 g_combh[(long long)Bsz * LQ * 2 * DIM];  // [32768,2048] mix|q
__device__ bf16 g_combl[(long long)Bsz * LQ * 2 * DIM];
__device__ bf16 g_wh[(long long)Bsz * LQ * LK];          // softmax weights
__device__ bf16 g_wl[(long long)Bsz * LQ * LK];
__device__ bf16 g_qryh[(long long)Bsz * LQ * DIM];
__device__ bf16 g_qryl[(long long)Bsz * LQ * DIM];
__device__ bf16 g_ctxh[(long long)Bsz * LK * DIM];
__device__ bf16 g_ctxl[(long long)Bsz * LK * DIM];
__device__ bf16 g_ctxTh[(long long)Bsz * DIM * LK];
__device__ bf16 g_ctxTl[(long long)Bsz * DIM * LK];
__device__ bf16 g_winh[DIM * DIM];
__device__ bf16 g_winl[DIM * DIM];
__device__ bf16 g_wouth[DIM * 2 * DIM];
__device__ bf16 g_woutl[DIM * 2 * DIM];
__device__ float g_meanf[Bsz * DIM];   // per-batch context mean (fp32)
__device__ bf16  g_mdh[Bsz * DIM];     // mean, split bf16
__device__ bf16  g_mdl[Bsz * DIM];
__device__ float g_biasd[Bsz * DIM];   // mean @ Wout_mix^T (fp32)

// ---------------------------------------------------------------------------
#define SW128(off) ((off) ^ (((off) >> 3) & 0x70))

__device__ __forceinline__ uint32_t smem_u32(const void* p) {
    uint32_t a;
    asm("{ .reg .u64 t; cvta.to.shared.u64 t, %1; cvt.u32.u64 %0, t; }"
        : "=r"(a) : "l"(p));
    return a;
}
__device__ __forceinline__ void cp16(uint32_t dst, const void* src) {
    asm volatile("cp.async.cg.shared.global [%0], [%1], 16;"
                 :: "r"(dst), "l"(src) : "memory");
}
#define CP_COMMIT() asm volatile("cp.async.commit_group;" ::: "memory")
#define CP_WAIT1()  asm volatile("cp.async.wait_group 1;" ::: "memory")

__device__ __forceinline__ void ldsm4(uint32_t* r, uint32_t addr) {
    asm volatile("ldmatrix.sync.aligned.m8n8.x4.shared.b16 {%0,%1,%2,%3}, [%4];"
                 : "=r"(r[0]), "=r"(r[1]), "=r"(r[2]), "=r"(r[3]) : "r"(addr));
}
__device__ __forceinline__ void mma16816(float* c, const uint32_t* a,
                                         uint32_t b0, uint32_t b1) {
    asm volatile(
        "mma.sync.aligned.m16n8k16.row.col.f32.bf16.bf16.f32 "
        "{%0,%1,%2,%3}, {%4,%5,%6,%7}, {%8,%9}, {%0,%1,%2,%3};"
        : "+f"(c[0]), "+f"(c[1]), "+f"(c[2]), "+f"(c[3])
        : "r"(a[0]), "r"(a[1]), "r"(a[2]), "r"(a[3]), "r"(b0), "r"(b1));
}

__device__ __forceinline__ void split2(float a, float b, bf162& hi, bf162& lo) {
    hi = __floats2bfloat162_rn(a, b);
    float2 hf = __bfloat1622float2(hi);
    lo = __floats2bfloat162_rn(a - hf.x, b - hf.y);
}

// ---------------------------------------------------------------------------
// Tile geometry: CTA 256x128, K-chunk 64 bf16 (128B rows, SW128), 512 threads.
// ---------------------------------------------------------------------------
#define TM 256
#define TN 128
#define KC 64
#define NTHR 512
#define OFF_AHI   0
#define OFF_ALO   32768
#define OFF_BHI   65536
#define OFF_BLO   81920
#define STAGE     98304
#define SM_TOTAL  (2 * STAGE)   // 196608

// ---------------------------------------------------------------------------
// split-bf16 mma.sync GEMM: C[m,n] = sum_k A[m,k]*B[n,k]
// EPI:  0 split-bf16 out, 1 length-mask fp32 out, 2 tanh fp32 out
// TRUNC:0 none
//       1 K4: dead tiles (m0>=ql) -> broadcast mean fill; other tiles K-trunc
//             at cl with per-row epilogue mean override for rows >= ql
//       2 K5: dead tiles ((m0&1023)>=ql) -> K restricted to q-half + fp32 bias
// Straddle tiles (K2/K4): warps whose whole row/col span is dead skip all
// ldsm+MMA work (results are overwritten in the epilogue anyway).
// ---------------------------------------------------------------------------
template <int EPI, int TRUNC>
__global__ __launch_bounds__(NTHR, 1)
void mma_gemm(const bf16* __restrict__ Ahi, const bf16* __restrict__ Alo,
              const bf16* __restrict__ Bhi, const bf16* __restrict__ Blo,
              float* __restrict__ Cf, bf16* __restrict__ Chi, bf16* __restrict__ Clo,
              int K, int lda, int ldb, int ldc,
              long long sA, long long sB, long long sC,
              const int* __restrict__ ql, const int* __restrict__ cl,
              const bf16* __restrict__ Dh, const bf16* __restrict__ Dl,
              const float* __restrict__ bias)
{
    extern __shared__ char smem[];
    const uint32_t sb = smem_u32(smem);
    const int tid  = threadIdx.x;
    const int wid  = tid >> 5;
    const int lane = tid & 31;
    const int bz = blockIdx.z;
    const int m0 = blockIdx.y * TM;
    const int n0 = blockIdx.x * TN;

    int qlen = 0, clen = 0;

    // K2 dead tiles: whole tile masked -> fill NEG_INF, no MMA.
    if (EPI == 1) {
        qlen = ql[bz]; clen = cl[bz];
        if (m0 >= qlen || n0 >= clen) {
            const float4 ninf = make_float4(NEG_INF, NEG_INF, NEG_INF, NEG_INF);
            float* base = Cf + (long long)bz * sC;
#pragma unroll 4
            for (int i = tid; i < TM * (TN / 4); i += NTHR) {
                const int r = i / (TN / 4);
                const int c = (i % (TN / 4)) * 4;
                *(float4*)(base + (long long)(m0 + r) * ldc + n0 + c) = ninf;
            }
            return;
        }
    }

    int S = K / KC;

    if (TRUNC == 1) {
        qlen = ql[bz]; clen = cl[bz];
        // dead tile: mix rows are the per-batch context mean -> broadcast fill
        if (m0 >= qlen) {
            for (int i = tid; i < TM * (TN / 2); i += NTHR) {
                const int r  = i / (TN / 2);
                const int c2 = (i % (TN / 2)) * 2;
                bf162 h = *(const bf162*)(Dh + bz * DIM + n0 + c2);
                bf162 l = *(const bf162*)(Dl + bz * DIM + n0 + c2);
                const long long o = (long long)bz * sC + (long long)(m0 + r) * ldc + n0 + c2;
                *(bf162*)(Chi + o) = h;
                *(bf162*)(Clo + o) = l;
            }
            return;
        }
        // live or straddle tile: weights beyond clen are exactly 0 for live
        // rows -> truncate K; dead rows (straddle) fixed up in the epilogue.
        const int se = (clen + KC - 1) / KC;
        if (se < S) S = se;
    }

    bool dead5 = false;
    int batch5 = 0;
    if (TRUNC == 2) {
        batch5 = m0 >> 10;           // TM=256 divides 1024; tile within one batch
        qlen = ql[batch5];
        if ((m0 & (LQ - 1)) >= qlen) { dead5 = true; S = S / 2; }
    }
    const int koff = dead5 ? (K / 2) : 0;   // skip mix half; bias covers it

    Ahi += (long long)bz * sA;  Alo += (long long)bz * sA;
    Bhi += (long long)bz * sB;  Blo += (long long)bz * sB;

    // A fill: 256 rows, 2 threads/row; 32 cols (4 x 16B) of hi and lo
    const int arow = tid >> 1;
    const bf16* Ah = Ahi + (long long)(m0 + arow) * lda + koff + (tid & 1) * 32;
    const bf16* Al = Alo + (long long)(m0 + arow) * lda + koff + (tid & 1) * 32;
    const uint32_t fbA = (uint32_t)(arow * 128 + (tid & 1) * 64);
    // B fill: 128 rows, 4 threads/row; 16 cols (2 x 16B) of hi and lo
    const int brow = tid >> 2;
    const bf16* Bh = Bhi + (long long)(n0 + brow) * ldb + koff + (tid & 3) * 16;
    const bf16* Bl = Blo + (long long)(n0 + brow) * ldb + koff + (tid & 3) * 16;
    const uint32_t fbB = (uint32_t)(brow * 128 + (tid & 3) * 32);

    auto issue = [&](int s) {
        const uint32_t st = sb + (s & 1) * STAGE;
        const int k0 = s * KC;
#pragma unroll
        for (int j = 0; j < 4; j++) {
            const uint32_t sw = SW128(fbA + j * 16);
            cp16(st + OFF_AHI + sw, Ah + k0 + j * 8);
            cp16(st + OFF_ALO + sw, Al + k0 + j * 8);
        }
#pragma unroll
        for (int j = 0; j < 2; j++) {
            const uint32_t sw = SW128(fbB + j * 16);
            cp16(st + OFF_BHI + sw, Bh + k0 + j * 8);
            cp16(st + OFF_BLO + sw, Bl + k0 + j * 8);
        }
        CP_COMMIT();
    };

    issue(0);
    if (S > 1) issue(1); else CP_COMMIT();

    // warp tile: 64x32 (warp grid 4 in M, 4 in N)
    const int wm = (wid & 3) * 64;
    const int wn = (wid >> 2) * 32;
    const int lrow8 = (lane & 7) + ((lane >> 3) & 1) * 8;
    const int lk16  = ((lane >> 4) & 1) * 16;

    // per-warp dead-region skip: warps whose whole span will be overwritten
    // in the epilogue (NEG_INF for K2, mean override for K4) do no MMA work.
    bool wlive = true;
    if (EPI == 1)   wlive = (wm < qlen - m0) && (wn < clen - n0);
    if (TRUNC == 1) wlive = (wm < qlen - m0);

    float acc[4][4][4];
#pragma unroll
    for (int mt = 0; mt < 4; mt++)
#pragma unroll
        for (int nt = 0; nt < 4; nt++)
#pragma unroll
            for (int i = 0; i < 4; i++) acc[mt][nt][i] = 0.f;

    for (int s = 0; s < S; s++) {
        CP_WAIT1();
        __syncthreads();

        if (wlive) {
            const uint32_t st = sb + (s & 1) * STAGE;
#pragma unroll
            for (int ks = 0; ks < KC / 16; ks++) {
                uint32_t bhi[2][4], blo[2][4];
#pragma unroll
                for (int bt = 0; bt < 2; bt++) {
                    uint32_t off = SW128((uint32_t)((wn + bt * 16 + lrow8) * 128 + ks * 32 + lk16));
                    ldsm4(bhi[bt], st + OFF_BHI + off);
                    ldsm4(blo[bt], st + OFF_BLO + off);
                }
#pragma unroll
                for (int mt = 0; mt < 4; mt++) {
                    uint32_t ahi[4], alo[4];
                    uint32_t off = SW128((uint32_t)((wm + mt * 16 + lrow8) * 128 + ks * 32 + lk16));
                    ldsm4(ahi, st + OFF_AHI + off);
                    ldsm4(alo, st + OFF_ALO + off);
#pragma unroll
                    for (int nt = 0; nt < 4; nt++)
                        mma16816(acc[mt][nt], ahi, bhi[nt >> 1][nt & 1], bhi[nt >> 1][(nt & 1) + 2]);
#pragma unroll
                    for (int nt = 0; nt < 4; nt++)
                        mma16816(acc[mt][nt], ahi, blo[nt >> 1][nt & 1], blo[nt >> 1][(nt & 1) + 2]);
#pragma unroll
                    for (int nt = 0; nt < 4; nt++)
                        mma16816(acc[mt][nt], alo, bhi[nt >> 1][nt & 1], bhi[nt >> 1][(nt & 1) + 2]);
                }
            }
        }
        __syncthreads();
        if (s + 2 < S) issue(s + 2);
    }

    // ------------------------- epilogue -------------------------
    const int rq = lane >> 2;
    const int cq = (lane & 3) * 2;

#pragma unroll
    for (int mt = 0; mt < 4; mt++) {
#pragma unroll
        for (int half = 0; half < 2; half++) {
            const int gm = m0 + wm + mt * 16 + rq + half * 8;
            const bool rowdead = (EPI == 1 || TRUNC == 1) && (gm >= qlen);
#pragma unroll
            for (int nt = 0; nt < 4; nt++) {
                const int gn = n0 + wn + nt * 8 + cq;
                float v0 = acc[mt][nt][half * 2 + 0];
                float v1 = acc[mt][nt][half * 2 + 1];
                const long long o = (long long)bz * sC + (long long)gm * ldc + gn;
                if (EPI == 0) {
                    if (TRUNC == 1 && rowdead) {
                        // straddle-tile dead row: mix = per-batch context mean
                        *(bf162*)(Chi + o) = *(const bf162*)(Dh + bz * DIM + gn);
                        *(bf162*)(Clo + o) = *(const bf162*)(Dl + bz * DIM + gn);
                    } else {
                        bf162 hp, lp;
                        split2(v0, v1, hp, lp);
                        *(bf162*)(Chi + o) = hp;
                        *(bf162*)(Clo + o) = lp;
                    }
                } else {
                    if (EPI == 1) {
                        if (rowdead || gn     >= clen) v0 = NEG_INF;
                        if (rowdead || gn + 1 >= clen) v1 = NEG_INF;
                    }
                    if (EPI == 2) {
                        if (TRUNC == 2 && dead5) {
                            v0 += bias[batch5 * DIM + gn];
                            v1 += bias[batch5 * DIM + gn + 1];
                        }
                        v0 = tanhf(v0); v1 = tanhf(v1);
                    }
                    *(float2*)(Cf + o) = make_float2(v0, v1);
                }
            }
        }
    }
}

// ---------------------------------------------------------------------------
// elementwise fp32 -> (hi, lo) bf16 split
// ---------------------------------------------------------------------------
__global__ __launch_bounds__(256)
void convert_split(const float4* __restrict__ src, bf162* __restrict__ hi,
                   bf162* __restrict__ lo, long long n4)
{
    const long long i = (long long)blockIdx.x * blockDim.x + threadIdx.x;
    if (i >= n4) return;
    float4 v = src[i];
    bf162 h0, l0, h1, l1;
    split2(v.x, v.y, h0, l0);
    split2(v.z, v.w, h1, l1);
    hi[2 * i] = h0; hi[2 * i + 1] = h1;
    lo[2 * i] = l0; lo[2 * i + 1] = l1;
}

// ---------------------------------------------------------------------------
// context: split-convert AND transposed split-convert in one pass.
// ---------------------------------------------------------------------------
__global__ __launch_bounds__(256)
void transpose_convert(const float* __restrict__ src,
                       bf16* __restrict__ ch, bf16* __restrict__ cl_,
                       bf16* __restrict__ th, bf16* __restrict__ tl)
{
    __shared__ float t[32][33];
    const long long bo = (long long)blockIdx.z * LK * DIM;
    const int x = blockIdx.x * 32 + threadIdx.x;
    const int y = blockIdx.y * 32 + threadIdx.y;
#pragma unroll
    for (int i = 0; i < 32; i += 8) {
        float v = src[bo + (long long)(y + i) * DIM + x];
        t[threadIdx.y + i][threadIdx.x] = v;
        bf16 h = __float2bfloat16_rn(v);
        bf16 l = __float2bfloat16_rn(v - __bfloat162float(h));
        ch[bo + (long long)(y + i) * DIM + x] = h;
        cl_[bo + (long long)(y + i) * DIM + x] = l;
    }
    __syncthreads();
    const int x2 = blockIdx.y * 32 + threadIdx.x;
    const int y2 = blockIdx.x * 32 + threadIdx.y;
#pragma unroll
    for (int i = 0; i < 32; i += 8) {
        float v = t[threadIdx.x][threadIdx.y + i];
        bf16 h = __float2bfloat16_rn(v);
        bf16 l = __float2bfloat16_rn(v - __bfloat162float(h));
        th[bo + (long long)(y2 + i) * LK + x2] = h;
        tl[bo + (long long)(y2 + i) * LK + x2] = l;
    }
}

// ---------------------------------------------------------------------------
// per-batch context mean over the Lk axis (fp32 + split bf16)
// ---------------------------------------------------------------------------
__global__ __launch_bounds__(256)
void ctx_mean(const float* __restrict__ ctx, float* __restrict__ meanf,
              bf16* __restrict__ mh, bf16* __restrict__ ml)
{
    const int b = blockIdx.y;
    const int d = blockIdx.x * 256 + threadIdx.x;
    const float* p = ctx + (long long)b * LK * DIM + d;
    float s = 0.f;
#pragma unroll 8
    for (int k = 0; k < LK; k++) s += p[(long long)k * DIM];
    s *= (1.0f / (float)LK);
    meanf[b * DIM + d] = s;
    bf16 h = __float2bfloat16_rn(s);
    mh[b * DIM + d] = h;
    ml[b * DIM + d] = __float2bfloat16_rn(s - __bfloat162float(h));
}

// ---------------------------------------------------------------------------
// bias[b][d] = sum_c mean[b][c] * W_out[d][c]  (mix half, fp32, warp-per-output)
// ---------------------------------------------------------------------------
__global__ __launch_bounds__(256)
void bias_gemm(const float* __restrict__ meanf, const float* __restrict__ Wout,
               float* __restrict__ bias)
{
    const int gw = (blockIdx.x * 256 + threadIdx.x) >> 5;   // global warp id
    const int lane = threadIdx.x & 31;
    if (gw >= Bsz * DIM) return;
    const int b = gw >> 10, d = gw & (DIM - 1);
    const float* m = meanf + b * DIM;
    const float* w = Wout + (long long)d * (2 * DIM);
    float s = 0.f;
#pragma unroll 4
    for (int c = lane; c < DIM; c += 32) s += m[c] * w[c];
#pragma unroll
    for (int o = 16; o > 0; o >>= 1) s += __shfl_xor_sync(0xffffffffu, s, o);
    if (lane == 0) bias[gw] = s;
}

// ---------------------------------------------------------------------------
// Row softmax over Lk=1024; emits split bf16 weights.
// Dead rows (r >= ql[b]) are exactly uniform 1/1024 -> constant fill.
// ---------------------------------------------------------------------------
__global__ __launch_bounds__(256)
void softmax_kernel(const float* __restrict__ scores,
                    bf16* __restrict__ wh, bf16* __restrict__ wl,
                    const int* __restrict__ ql)
{
    const long long row = blockIdx.x;
    const int t = threadIdx.x;
    const int b = (int)(row >> 10);
    const int r = (int)(row & (LQ - 1));

    if (r >= ql[b]) {
        const bf162 h = __floats2bfloat162_rn(1.0f / 1024.0f, 1.0f / 1024.0f);
        const bf162 z = __floats2bfloat162_rn(0.0f, 0.0f);
        *(bf162*)(wh + row * LK + 2 * t) = h;
        *(bf162*)(wl + row * LK + 2 * t) = z;
        *(bf162*)(wh + row * LK + 2 * t + 512) = h;
        *(bf162*)(wl + row * LK + 2 * t + 512) = z;
        return;
    }

    const float* s = scores + row * LK;
    float2 x0 = *(const float2*)(s + 2 * t);
    float2 x1 = *(const float2*)(s + 2 * t + 512);
    float lmax = fmaxf(fmaxf(x0.x, x0.y), fmaxf(x1.x, x1.y));

    __shared__ float red[8];
#pragma unroll
    for (int o = 16; o > 0; o >>= 1) lmax = fmaxf(lmax, __shfl_xor_sync(0xffffffffu, lmax, o));
    if ((t & 31) == 0) red[t >> 5] = lmax;
    __syncthreads();
    if (t < 32) {
        float m = (t < 8) ? red[t] : -INFINITY;
#pragma unroll
        for (int o = 4; o > 0; o >>= 1) m = fmaxf(m, __shfl_xor_sync(0xffffffffu, m, o));
        if (t == 0) red[0] = m;
    }
    __syncthreads();
    const float m = red[0];

    float e0 = __expf(x0.x - m), e1 = __expf(x0.y - m);
    float e2 = __expf(x1.x - m), e3 = __expf(x1.y - m);
    float lsum = e0 + e1 + e2 + e3;
#pragma unroll
    for (int o = 16; o > 0; o >>= 1) lsum += __shfl_xor_sync(0xffffffffu, lsum, o);
    __shared__ float red2[8];
    if ((t & 31) == 0) red2[t >> 5] = lsum;
    __syncthreads();
    if (t < 32) {
        float x = (t < 8) ? red2[t] : 0.f;
#pragma unroll
        for (int o = 4; o > 0; o >>= 1) x += __shfl_xor_sync(0xffffffffu, x, o);
        if (t == 0) red2[0] = x;
    }
    __syncthreads();
    const float inv = 1.0f / red2[0];

    bf162 h, l;
    split2(e0 * inv, e1 * inv, h, l);
    *(bf162*)(wh + row * LK + 2 * t) = h;
    *(bf162*)(wl + row * LK + 2 * t) = l;
    split2(e2 * inv, e3 * inv, h, l);
    *(bf162*)(wh + row * LK + 2 * t + 512) = h;
    *(bf162*)(wl + row * LK + 2 * t + 512) = l;
}

// ---------------------------------------------------------------------------
extern "C" void kernel_launch(void* const* d_in, const int* in_sizes, int n_in,
                              void* d_out, int out_size)
{
    const float* query   = (const float*)d_in[0];
    const float* context = (const float*)d_in[1];
    const int*   ql      = (const int*)d_in[2];
    const int*   cl      = (const int*)d_in[3];
    const float* W_in    = (const float*)d_in[4];
    const float* W_out   = (const float*)d_in[5];

    float* out        = (float*)d_out;
    float* scores_out = out + (long long)Bsz * LQ * DIM;

    bf16 *combh, *combl, *wh, *wl, *qryh, *qryl, *ctxh, *ctxl, *ctxTh, *ctxTl;
    bf16 *winh, *winl, *wouth, *woutl, *mdh, *mdl;
    float *meanf, *biasd;
    cudaGetSymbolAddress((void**)&combh, g_combh);
    cudaGetSymbolAddress((void**)&combl, g_combl);
    cudaGetSymbolAddress((void**)&wh,    g_wh);
    cudaGetSymbolAddress((void**)&wl,    g_wl);
    cudaGetSymbolAddress((void**)&qryh,  g_qryh);
    cudaGetSymbolAddress((void**)&qryl,  g_qryl);
    cudaGetSymbolAddress((void**)&ctxh,  g_ctxh);
    cudaGetSymbolAddress((void**)&ctxl,  g_ctxl);
    cudaGetSymbolAddress((void**)&ctxTh, g_ctxTh);
    cudaGetSymbolAddress((void**)&ctxTl, g_ctxTl);
    cudaGetSymbolAddress((void**)&winh,  g_winh);
    cudaGetSymbolAddress((void**)&winl,  g_winl);
    cudaGetSymbolAddress((void**)&wouth, g_wouth);
    cudaGetSymbolAddress((void**)&woutl, g_woutl);
    cudaGetSymbolAddress((void**)&mdh,   g_mdh);
    cudaGetSymbolAddress((void**)&mdl,   g_mdl);
    cudaGetSymbolAddress((void**)&meanf, g_meanf);
    cudaGetSymbolAddress((void**)&biasd, g_biasd);

    cudaFuncSetAttribute(mma_gemm<0, 0>, cudaFuncAttributeMaxDynamicSharedMemorySize, SM_TOTAL);
    cudaFuncSetAttribute(mma_gemm<0, 1>, cudaFuncAttributeMaxDynamicSharedMemorySize, SM_TOTAL);
    cudaFuncSetAttribute(mma_gemm<1, 0>, cudaFuncAttributeMaxDynamicSharedMemorySize, SM_TOTAL);
    cudaFuncSetAttribute(mma_gemm<2, 2>, cudaFuncAttributeMaxDynamicSharedMemorySize, SM_TOTAL);

    // per-half strides (batch offsets)
    const long long QOFF  = (long long)HB * LQ * DIM;      // query/out/q-arrays
    const long long COFF  = (long long)HB * LQ * 2 * DIM;  // comb arrays
    const long long SOFF  = (long long)HB * LQ * LK;       // scores/weights
    const long long XOFF  = (long long)HB * LK * DIM;      // ctx / ctxT
    const long long MOFF  = (long long)HB * DIM;           // mean/bias

    static cudaStream_t s1 = nullptr, s2 = nullptr;
    static cudaEvent_t  ef = nullptr, e1 = nullptr, e2 = nullptr,
                        eqw = nullptr, ek5b = nullptr;
    if (s1 == nullptr) {
        cudaStreamCreateWithFlags(&s1, cudaStreamNonBlocking);
        cudaStreamCreateWithFlags(&s2, cudaStreamNonBlocking);
        cudaEventCreateWithFlags(&ef,   cudaEventDisableTiming);
        cudaEventCreateWithFlags(&e1,   cudaEventDisableTiming);
        cudaEventCreateWithFlags(&e2,   cudaEventDisableTiming);
        cudaEventCreateWithFlags(&eqw,  cudaEventDisableTiming);
        cudaEventCreateWithFlags(&ek5b, cudaEventDisableTiming);
    }

    cudaEventRecord(ef, 0);
    cudaStreamWaitEvent(s1, ef, 0);
    cudaStreamWaitEvent(s2, ef, 0);

    // ---- branch s1: context transforms -> mean -> dead-row bias ----
    transpose_convert<<<dim3(32, 32, Bsz), dim3(32, 8), 0, s1>>>(
        context, ctxh, ctxl, ctxTh, ctxTl);
    ctx_mean<<<dim3(DIM / 256, Bsz), 256, 0, s1>>>(context, meanf, mdh, mdl);
    bias_gemm<<<(Bsz * DIM * 32) / 256, 256, 0, s1>>>(meanf, W_out, biasd);
    cudaEventRecord(e1, s1);

    const long long h4 = (long long)HB * LQ * DIM / 4;   // fp32 float4s per half

    // ---- main: W_in conversion (shared) + query half A conversion ----
    {
        long long w4 = (long long)DIM * DIM / 4;
        convert_split<<<(unsigned)((w4 + 255) / 256), 256>>>(
            (const float4*)W_in, (bf162*)winh, (bf162*)winl, w4);
        cudaEventRecord(eqw, 0);   // W_in ready
        convert_split<<<(unsigned)((h4 + 255) / 256), 256>>>(
            (const float4*)query, (bf162*)qryh, (bf162*)qryl, h4);
    }

    // ---- branch s2: W_out conversion + query half B, then pipeline B ----
    {
        long long o4 = (long long)DIM * 2 * DIM / 4;
        convert_split<<<(unsigned)((o4 + 255) / 256), 256, 0, s2>>>(
            (const float4*)W_out, (bf162*)wouth, (bf162*)woutl, o4);
        cudaEventRecord(e2, s2);
        convert_split<<<(unsigned)((h4 + 255) / 256), 256, 0, s2>>>(
            (const float4*)(query + QOFF), (bf162*)(qryh + QOFF),
            (bf162*)(qryl + QOFF), h4);
    }
    cudaStreamWaitEvent(s2, eqw, 0);   // W_in ready for K1b

    const unsigned MYH = (unsigned)(HB * LQ / TM);   // 64: M-tiles per half

    // K1b
    mma_gemm<0, 0><<<dim3(DIM / TN, MYH, 1), NTHR, SM_TOTAL, s2>>>(
        qryh + QOFF, qryl + QOFF, winh, winl, nullptr,
        combh + DIM + COFF, combl + DIM + COFF,
        DIM, DIM, DIM, 2 * DIM, 0, 0, 0, nullptr, nullptr,
        nullptr, nullptr, nullptr);
    cudaStreamWaitEvent(s2, e1, 0);
    // K2b
    mma_gemm<1, 0><<<dim3(LK / TN, LQ / TM, HB), NTHR, SM_TOTAL, s2>>>(
        combh + DIM + COFF, combl + DIM + COFF, ctxh + XOFF, ctxl + XOFF,
        scores_out + SOFF, nullptr, nullptr,
        DIM, 2 * DIM, DIM, LK,
        (long long)LQ * 2 * DIM, (long long)LK * DIM, (long long)LQ * LK,
        ql + HB, cl + HB, nullptr, nullptr, nullptr);
    // SMb
    softmax_kernel<<<(unsigned)(HB * LQ), 256, 0, s2>>>(
        scores_out + SOFF, wh + SOFF, wl + SOFF, ql + HB);
    // K4b
    mma_gemm<0, 1><<<dim3(DIM / TN, LQ / TM, HB), NTHR, SM_TOTAL, s2>>>(
        wh + SOFF, wl + SOFF, ctxTh + XOFF, ctxTl + XOFF, nullptr,
        combh + COFF, combl + COFF,
        LK, LK, LK, 2 * DIM,
        (long long)LQ * LK, (long long)DIM * LK, (long long)LQ * 2 * DIM,
        ql + HB, cl + HB, mdh + MOFF, mdl + MOFF, nullptr);
    // K5b (wout ready: same stream as its conversion)
    mma_gemm<2, 2><<<dim3(DIM / TN, MYH, 1), NTHR, SM_TOTAL, s2>>>(
        combh + COFF, combl + COFF, wouth, woutl, out + QOFF, nullptr, nullptr,
        2 * DIM, 2 * DIM, 2 * DIM, DIM, 0, 0, 0, ql + HB, nullptr,
        nullptr, nullptr, biasd + MOFF);
    cudaEventRecord(ek5b, s2);

    // ---- main: pipeline A (batches 0..15) ----
    // K1a
    mma_gemm<0, 0><<<dim3(DIM / TN, MYH, 1), NTHR, SM_TOTAL>>>(
        qryh, qryl, winh, winl, nullptr, combh + DIM, combl + DIM,
        DIM, DIM, DIM, 2 * DIM, 0, 0, 0, nullptr, nullptr,
        nullptr, nullptr, nullptr);
    cudaStreamWaitEvent(0, e1, 0);
    // K2a
    mma_gemm<1, 0><<<dim3(LK / TN, LQ / TM, HB), NTHR, SM_TOTAL>>>(
        combh + DIM, combl + DIM, ctxh, ctxl, scores_out, nullptr, nullptr,
        DIM, 2 * DIM, DIM, LK,
        (long long)LQ * 2 * DIM, (long long)LK * DIM, (long long)LQ * LK,
        ql, cl, nullptr, nullptr, nullptr);
    // SMa
    softmax_kernel<<<(unsigned)(HB * LQ), 256>>>(scores_out, wh, wl, ql);
    // K4a
    mma_gemm<0, 1><<<dim3(DIM / TN, LQ / TM, HB), NTHR, SM_TOTAL>>>(
        wh, wl, ctxTh, ctxTl, nullptr, combh, combl,
        LK, LK, LK, 2 * DIM,
        (long long)LQ * LK, (long long)DIM * LK, (long long)LQ * 2 * DIM,
        ql, cl, mdh, mdl, nullptr);
    // K5a (needs W_out conversion from s2)
    cudaStreamWaitEvent(0, e2, 0);
    mma_gemm<2, 2><<<dim3(DIM / TN, MYH, 1), NTHR, SM_TOTAL>>>(
        combh, combl, wouth, woutl, out, nullptr, nullptr,
        2 * DIM, 2 * DIM, 2 * DIM, DIM, 0, 0, 0, ql, nullptr,
        nullptr, nullptr, biasd);

    // join pipeline B before returning
    cudaStreamWaitEvent(0, ek5b, 0);
}